// round 4
// baseline (speedup 1.0000x reference)
#include <cuda_runtime.h>
#include <cstdint>

#define M    100000
#define NQ   256
#define D    128
#define KNN  100
#define BB   4
#define TT   64
#define CH   8
#define CHSZ (M / CH)     // 12500
#define CAND 2048         // candidate capacity per chunk

// ---------------- device scratch (no allocs allowed) ----------------
static __device__ float        g_qn[NQ];
static __device__ float        g_tn[M];
static __device__ unsigned int g_key[(size_t)NQ * M];               // approx sortable keys
static __device__ unsigned long long g_part[NQ * CH * KNN];
static __device__ int          g_idx[NQ * KNN];
static __device__ float        g_emit[NQ * KNN];
static __device__ float        g_states[(size_t)NQ * KNN * D];
static __device__ float        g_trans[(size_t)BB * (TT - 1) * KNN * KNN];

__device__ __forceinline__ unsigned int f2key(float f) {
    unsigned int u = __float_as_uint(f);
    return (u & 0x80000000u) ? ~u : (u | 0x80000000u);
}
__device__ __forceinline__ float key2f(unsigned int k) {
    unsigned int u = (k & 0x80000000u) ? (k & 0x7fffffffu) : ~k;
    return __uint_as_float(u);
}

__device__ __forceinline__ void mma_tf32(float* d, const unsigned* a, const unsigned* b) {
    asm volatile(
        "mma.sync.aligned.m16n8k8.row.col.f32.tf32.tf32.f32 "
        "{%0,%1,%2,%3}, {%4,%5,%6,%7}, {%8,%9}, {%0,%1,%2,%3};"
        : "+f"(d[0]), "+f"(d[1]), "+f"(d[2]), "+f"(d[3])
        : "r"(a[0]), "r"(a[1]), "r"(a[2]), "r"(a[3]), "r"(b[0]), "r"(b[1]));
}

// ---------------- norms ----------------
__global__ void norms_kernel(const float* __restrict__ Q, const float* __restrict__ Tg) {
    int i = blockIdx.x * blockDim.x + threadIdx.x;
    if (i < M) {
        const float4* p = (const float4*)(Tg + (size_t)i * D);
        float acc = 0.f;
#pragma unroll
        for (int k = 0; k < D / 4; k++) {
            float4 v = p[k];
            acc += v.x * v.x + v.y * v.y + v.z * v.z + v.w * v.w;
        }
        g_tn[i] = acc;
    } else if (i < M + NQ) {
        int q = i - M;
        const float4* p = (const float4*)(Q + (size_t)q * D);
        float acc = 0.f;
#pragma unroll
        for (int k = 0; k < D / 4; k++) {
            float4 v = p[k];
            acc += v.x * v.x + v.y * v.y + v.z * v.z + v.w * v.w;
        }
        g_qn[q] = acc;
    }
}

// ---------------- approx distance GEMM on TF32 tensor cores ----------------
// block tile 128(q) x 128(t), K=128 staged once in smem, 8 warps, warp tile 32x64.
__global__ __launch_bounds__(256, 1)
void dist_approx_kernel(const float* __restrict__ Q, const float* __restrict__ Tg) {
    extern __shared__ __align__(16) float dsm[];
    float* Qs = dsm;               // [128][132]
    float* Ts = dsm + 128 * 132;   // [128][132]
    __shared__ float s_qn[128], s_tn[128];
    int tid = threadIdx.x;
    int q0 = blockIdx.y * 128, t0 = blockIdx.x * 128;

    for (int i = tid; i < 128 * 32; i += 256) {
        int row = i >> 5, c4 = (i & 31) << 2;
        *(float4*)&Qs[row * 132 + c4] = *(const float4*)&Q[(size_t)(q0 + row) * D + c4];
        float4 tv = make_float4(0.f, 0.f, 0.f, 0.f);
        if (t0 + row < M) tv = *(const float4*)&Tg[(size_t)(t0 + row) * D + c4];
        *(float4*)&Ts[row * 132 + c4] = tv;
    }
    if (tid < 128) {
        s_qn[tid] = g_qn[q0 + tid];
        s_tn[tid] = (t0 + tid < M) ? g_tn[t0 + tid] : 0.f;
    }
    __syncthreads();

    int wid = tid >> 5, lane = tid & 31;
    int g = lane >> 2, t = lane & 3;
    int m0 = (wid >> 1) * 32, n0 = (wid & 1) * 64;

    float acc[2][8][4];
#pragma unroll
    for (int mi = 0; mi < 2; mi++)
#pragma unroll
        for (int ni = 0; ni < 8; ni++)
#pragma unroll
            for (int r = 0; r < 4; r++) acc[mi][ni][r] = 0.f;

    for (int kc = 0; kc < 16; kc++) {
        int k0 = kc * 8;
        unsigned a[2][4], b[8][2];
#pragma unroll
        for (int mi = 0; mi < 2; mi++) {
            const float* base = &Qs[(m0 + mi * 16 + g) * 132 + k0 + t];
            a[mi][0] = __float_as_uint(base[0]);
            a[mi][1] = __float_as_uint(base[8 * 132]);
            a[mi][2] = __float_as_uint(base[4]);
            a[mi][3] = __float_as_uint(base[8 * 132 + 4]);
        }
#pragma unroll
        for (int ni = 0; ni < 8; ni++) {
            const float* base = &Ts[(n0 + ni * 8 + g) * 132 + k0 + t];
            b[ni][0] = __float_as_uint(base[0]);
            b[ni][1] = __float_as_uint(base[4]);
        }
#pragma unroll
        for (int mi = 0; mi < 2; mi++)
#pragma unroll
            for (int ni = 0; ni < 8; ni++)
                mma_tf32(acc[mi][ni], a[mi], b[ni]);
    }

    // epilogue: d = qn + tn - 2*dot -> sortable key, 8B coalesced stores
#pragma unroll
    for (int mi = 0; mi < 2; mi++)
#pragma unroll
        for (int half = 0; half < 2; half++) {
            int qr = m0 + mi * 16 + g + half * 8;
            float qn = s_qn[qr];
            unsigned int* dst = g_key + (size_t)(q0 + qr) * M;
#pragma unroll
            for (int ni = 0; ni < 8; ni++) {
                int tc = n0 + ni * 8 + 2 * t;
                int gtc = t0 + tc;
                if (gtc < M) {
                    float d0 = qn + s_tn[tc]     - 2.f * acc[mi][ni][half * 2 + 0];
                    float d1 = qn + s_tn[tc + 1] - 2.f * acc[mi][ni][half * 2 + 1];
                    *(uint2*)&dst[gtc] = make_uint2(f2key(d0), f2key(d1));
                }
            }
        }
}

// ---------------- per-chunk: approx radix-select -> candidates -> exact refine ----------------
__global__ void select_part_kernel(const float* __restrict__ Q, const float* __restrict__ Tg) {
    extern __shared__ __align__(16) unsigned int sp[];
    unsigned int* skey = sp;                                    // CHSZ approx keys
    unsigned int* hist = sp + CHSZ;                             // 2048
    unsigned int* cand = hist + 2048;                           // CAND chunk-local idx
    unsigned long long* buf = (unsigned long long*)(cand + CAND);  // CAND u64
    float* qrow_s = (float*)(buf + CAND);                       // 128 floats
    __shared__ unsigned int scanbuf[256];
    __shared__ unsigned int s_prefix, s_cnt;
    __shared__ int s_kneed;

    int q = blockIdx.y;
    int c0 = blockIdx.x * CHSZ;
    int tid = threadIdx.x;
    const unsigned int* krow = g_key + (size_t)q * M + c0;

    for (int j = tid; j < CHSZ / 4; j += 256)
        *(uint4*)&skey[j * 4] = *(const uint4*)&krow[j * 4];
    if (tid < 32)
        *(float4*)&qrow_s[tid * 4] = *(const float4*)&Q[(size_t)q * D + tid * 4];
    if (tid == 0) { s_prefix = 0u; s_kneed = KNN; }
    __syncthreads();

    // exact 100th-smallest APPROX key in this chunk (3-pass radix over smem)
    const int shifts[3]  = {21, 10, 0};
    const int bitsArr[3] = {11, 11, 10};
    for (int p = 0; p < 3; p++) {
        int shift = shifts[p];
        int nb = 1 << bitsArr[p];
        for (int i = tid; i < nb; i += 256) hist[i] = 0u;
        __syncthreads();
        unsigned int prefix = s_prefix;
        int top = shift + bitsArr[p];
        for (int j = tid; j < CHSZ; j += 256) {
            unsigned int key = skey[j];
            bool ok = (top >= 32) || ((key >> top) == (prefix >> top));
            if (ok) {
                unsigned int bin = (key >> shift) & (unsigned int)(nb - 1);
                unsigned int mm = __match_any_sync(__activemask(), bin);
                if ((int)(tid & 31) == __ffs(mm) - 1) atomicAdd(&hist[bin], (unsigned)__popc(mm));
            }
        }
        __syncthreads();
        int chunk = nb / 256;
        unsigned int ssum = 0u;
        for (int i = 0; i < chunk; i++) ssum += hist[tid * chunk + i];
        scanbuf[tid] = ssum;
        __syncthreads();
        for (int off = 1; off < 256; off <<= 1) {
            unsigned int a = scanbuf[tid];
            unsigned int b = (tid >= off) ? scanbuf[tid - off] : 0u;
            __syncthreads();
            scanbuf[tid] = a + b;
            __syncthreads();
        }
        int kneed = s_kneed;
        unsigned int excl = (tid == 0) ? 0u : scanbuf[tid - 1];
        unsigned int incl = scanbuf[tid];
        __syncthreads();
        if ((int)excl < kneed && kneed <= (int)incl) {
            unsigned int c = excl;
            for (int i = 0; i < chunk; i++) {
                unsigned int h = hist[tid * chunk + i];
                c += h;
                if (kneed <= (int)c) {
                    s_prefix = prefix | ((unsigned int)(tid * chunk + i) << shift);
                    s_kneed = kneed - (int)(c - h);
                    break;
                }
            }
        }
        __syncthreads();
    }

    float dkth = key2f(s_prefix);

    // collect candidates within margin of approx kth (fallback margin on overflow)
    int n = 0;
    for (int att = 0; att < 2; att++) {
        if (tid == 0) s_cnt = 0u;
        __syncthreads();
        unsigned int thresh = f2key(dkth + ((att == 0) ? 4.0f : 0.5f));
        for (int j = tid; j < CHSZ; j += 256) {
            if (skey[j] <= thresh) {
                unsigned int pos = atomicAdd(&s_cnt, 1u);
                if (pos < CAND) cand[pos] = (unsigned int)j;
            }
        }
        __syncthreads();
        n = (int)s_cnt;
        if (n <= CAND) break;
        __syncthreads();
    }
    if (n > CAND) n = CAND;

    // exact fp32 recompute for candidates
    float qn = g_qn[q];
    for (int c = tid; c < n; c += 256) {
        int j = (int)cand[c];
        const float* trow = Tg + (size_t)(c0 + j) * D;
        float a0 = 0.f, a1 = 0.f, a2 = 0.f, a3 = 0.f;
#pragma unroll
        for (int k4 = 0; k4 < 32; k4++) {
            float4 tv = *(const float4*)&trow[k4 * 4];
            float4 qv = *(const float4*)&qrow_s[k4 * 4];
            a0 = fmaf(qv.x, tv.x, a0);
            a1 = fmaf(qv.y, tv.y, a1);
            a2 = fmaf(qv.z, tv.z, a2);
            a3 = fmaf(qv.w, tv.w, a3);
        }
        float d = qn + g_tn[c0 + j] - 2.f * ((a0 + a1) + (a2 + a3));
        buf[c] = ((unsigned long long)f2key(d) << 32) | (unsigned int)(c0 + j);
    }
    __syncthreads();

    int size = 128;
    while (size < n) size <<= 1;
    for (int i = tid; i < size; i += 256)
        if (i >= n) buf[i] = 0xFFFFFFFFFFFFFFFFull;
    __syncthreads();

    for (int k2 = 2; k2 <= size; k2 <<= 1) {
        for (int j2 = k2 >> 1; j2 > 0; j2 >>= 1) {
            for (int i = tid; i < size; i += 256) {
                int l = i ^ j2;
                if (l > i) {
                    unsigned long long a = buf[i], b = buf[l];
                    bool up = ((i & k2) == 0);
                    if ((a > b) == up) { buf[i] = b; buf[l] = a; }
                }
            }
            __syncthreads();
        }
    }

    unsigned long long* dst = g_part + (q * CH + blockIdx.x) * KNN;
    if (tid < KNN) dst[tid] = buf[tid];
}

// ---------------- merge 8x100 chunk winners -> global top-100 ----------------
__global__ void select_merge_kernel() {
    __shared__ unsigned long long buf[1024];
    __shared__ float sred[256];
    __shared__ float s_dmin;
    int q = blockIdx.x;
    int tid = threadIdx.x;
    const unsigned long long* src = g_part + q * CH * KNN;
    for (int i = tid; i < 1024; i += 256)
        buf[i] = (i < CH * KNN) ? src[i] : 0xFFFFFFFFFFFFFFFFull;
    __syncthreads();
    for (int k2 = 2; k2 <= 1024; k2 <<= 1) {
        for (int j2 = k2 >> 1; j2 > 0; j2 >>= 1) {
            for (int i = tid; i < 1024; i += 256) {
                int l = i ^ j2;
                if (l > i) {
                    unsigned long long a = buf[i], b = buf[l];
                    bool up = ((i & k2) == 0);
                    if ((a > b) == up) { buf[i] = b; buf[l] = a; }
                }
            }
            __syncthreads();
        }
    }
    if (tid == 0) s_dmin = key2f((unsigned int)(buf[0] >> 32));
    __syncthreads();
    float dmin = s_dmin;
    float myex = 0.f; int myidx = 0;
    if (tid < KNN) {
        unsigned long long e = buf[tid];
        myidx = (int)(unsigned int)(e & 0xffffffffull);
        float d = key2f((unsigned int)(e >> 32));
        myex = expf(dmin - d);
    }
    sred[tid] = (tid < KNN) ? myex : 0.f;
    __syncthreads();
    for (int off = 128; off > 0; off >>= 1) {
        if (tid < off) sred[tid] += sred[tid + off];
        __syncthreads();
    }
    float ssum = sred[0];
    if (tid < KNN) {
        g_emit[q * KNN + tid] = myex / ssum;
        g_idx[q * KNN + tid] = myidx;
    }
}

// ---------------- states gather ----------------
__global__ void gather_states_kernel(const float* __restrict__ Tg) {
    int n = blockIdx.x * blockDim.x + threadIdx.x;
    if (n >= NQ * KNN * (D / 4)) return;
    int row = n / (D / 4);
    int c = n % (D / 4);
    int tgt = g_idx[row];
    float4 v = *(const float4*)&Tg[(size_t)tgt * D + c * 4];
    *(float4*)&g_states[(size_t)row * D + c * 4] = v;
}

// ---------------- transitions: exp(-||a_i - b_j||^2) ----------------
__global__ void trans_kernel() {
    extern __shared__ __align__(16) float s[];
    float* sA = s;
    float* sB = s + D * KNN;
    float* an = s + 2 * D * KNN;
    float* bn = an + KNN;
    int bt = blockIdx.x;
    int b = bt / (TT - 1), tl = bt % (TT - 1);
    int qA = b * TT + tl, qB = qA + 1;
    for (int n = threadIdx.x; n < KNN * D; n += blockDim.x) {
        int i = n / D, k = n % D;
        sA[k * KNN + i] = g_states[(size_t)qA * KNN * D + n];
        sB[k * KNN + i] = g_states[(size_t)qB * KNN * D + n];
    }
    __syncthreads();
    for (int i = threadIdx.x; i < 2 * KNN; i += blockDim.x) {
        int ii = (i < KNN) ? i : (i - KNN);
        const float* sp = (i < KNN) ? sA : sB;
        float acc = 0.f;
        for (int k = 0; k < D; k++) { float x = sp[k * KNN + ii]; acc += x * x; }
        if (i < KNN) an[ii] = acc; else bn[ii] = acc;
    }
    __syncthreads();
    float* trow = g_trans + (size_t)bt * KNN * KNN;
    for (int t4 = threadIdx.x; t4 < 625; t4 += blockDim.x) {
        int i0 = (t4 / 25) * 4, j0 = (t4 % 25) * 4;
        float acc[4][4] = {};
        for (int k = 0; k < D; k++) {
            float4 a  = *(const float4*)&sA[k * KNN + i0];
            float4 b4 = *(const float4*)&sB[k * KNN + j0];
            acc[0][0] += a.x * b4.x; acc[0][1] += a.x * b4.y; acc[0][2] += a.x * b4.z; acc[0][3] += a.x * b4.w;
            acc[1][0] += a.y * b4.x; acc[1][1] += a.y * b4.y; acc[1][2] += a.y * b4.z; acc[1][3] += a.y * b4.w;
            acc[2][0] += a.z * b4.x; acc[2][1] += a.z * b4.y; acc[2][2] += a.z * b4.z; acc[2][3] += a.z * b4.w;
            acc[3][0] += a.w * b4.x; acc[3][1] += a.w * b4.y; acc[3][2] += a.w * b4.z; acc[3][3] += a.w * b4.w;
        }
#pragma unroll
        for (int ii = 0; ii < 4; ii++)
#pragma unroll
            for (int jj = 0; jj < 4; jj++) {
                int i = i0 + ii, j = j0 + jj;
                float dd = an[i] + bn[j] - 2.f * acc[ii][jj];
                trow[i * KNN + j] = expf(-dd);
            }
    }
}

// ---------------- viterbi (512 threads, i-loop split 4-way) ----------------
__global__ void viterbi_kernel(const float* __restrict__ Tg, float* __restrict__ out) {
    int b = blockIdx.x;
    int tid = threadIdx.x;
    int j = tid & 127, s = tid >> 7;
    __shared__ float v[128];
    __shared__ float part[4][128];
    __shared__ unsigned char parti[4][128];
    __shared__ float red[128];
    __shared__ unsigned char bp[TT - 1][KNN];
    __shared__ int path[TT];
    if (s == 0) v[j] = (j < KNN) ? g_emit[(b * TT) * KNN + j] : 0.f;
    __syncthreads();
    for (int t = 1; t < TT; t++) {
        const float* tr = g_trans + (size_t)(b * (TT - 1) + t - 1) * KNN * KNN;
        float best = -1.f; int back = 0;
        if (j < KNN) {
            int i0 = s * 25;
#pragma unroll
            for (int ii = 0; ii < 25; ii++) {
                int i = i0 + ii;
                float sc = v[i] * tr[i * KNN + j];
                if (sc > best) { best = sc; back = i; }
            }
        }
        part[s][j] = best; parti[s][j] = (unsigned char)back;
        __syncthreads();
        if (s == 0) {
            float em = (j < KNN) ? g_emit[(b * TT + t) * KNN + j] : 0.f;
            float bb = part[0][j]; int bk = parti[0][j];
#pragma unroll
            for (int ss = 1; ss < 4; ss++)
                if (part[ss][j] > bb) { bb = part[ss][j]; bk = parti[ss][j]; }
            if (j < KNN) bp[t - 1][j] = (unsigned char)bk;
            float vn = (j < KNN) ? bb * em : 0.f;
            red[j] = vn;
            part[0][j] = vn;
        }
        __syncthreads();
        for (int off = 64; off > 0; off >>= 1) {
            if (tid < off) red[tid] = fmaxf(red[tid], red[tid + off]);
            __syncthreads();
        }
        float m = fmaxf(red[0], 1e-30f);
        __syncthreads();
        if (s == 0) v[j] = part[0][j] / m;
        __syncthreads();
    }
    if (tid == 0) {
        float bv = v[0]; int last = 0;
        for (int jj = 1; jj < KNN; jj++) if (v[jj] > bv) { bv = v[jj]; last = jj; }
        path[TT - 1] = last;
        int idx = last;
        for (int t = TT - 2; t >= 0; t--) { idx = bp[t][idx]; path[t] = idx; }
    }
    __syncthreads();
    for (int n = tid; n < TT * D; n += 512) {
        int t = n / D, d2 = n % D;
        int row = g_idx[(b * TT + t) * KNN + path[t]];
        out[(size_t)(b * TT + t) * D + d2] = Tg[(size_t)row * D + d2];
    }
}

// ---------------- launch ----------------
extern "C" void kernel_launch(void* const* d_in, const int* in_sizes, int n_in,
                              void* d_out, int out_size) {
    (void)in_sizes; (void)n_in; (void)out_size;
    const float* Q  = (const float*)d_in[0];
    const float* Tg = (const float*)d_in[1];
    float* out = (float*)d_out;

    const int trans_smem = (2 * D * KNN + 2 * KNN) * (int)sizeof(float);            // 103200 B
    const int dist_smem  = 2 * 128 * 132 * (int)sizeof(float);                      // 135168 B
    const int part_smem  = (CHSZ + 2048 + CAND) * 4 + CAND * 8 + 128 * 4;           // 83280 B
    cudaFuncSetAttribute(trans_kernel, cudaFuncAttributeMaxDynamicSharedMemorySize, trans_smem);
    cudaFuncSetAttribute(dist_approx_kernel, cudaFuncAttributeMaxDynamicSharedMemorySize, dist_smem);
    cudaFuncSetAttribute(select_part_kernel, cudaFuncAttributeMaxDynamicSharedMemorySize, part_smem);

    norms_kernel<<<(M + NQ + 255) / 256, 256>>>(Q, Tg);
    dist_approx_kernel<<<dim3((M + 127) / 128, NQ / 128), 256, dist_smem>>>(Q, Tg);
    select_part_kernel<<<dim3(CH, NQ), 256, part_smem>>>(Q, Tg);
    select_merge_kernel<<<NQ, 256>>>();
    gather_states_kernel<<<(NQ * KNN * (D / 4) + 255) / 256, 256>>>(Tg);
    trans_kernel<<<BB * (TT - 1), 256, trans_smem>>>();
    viterbi_kernel<<<BB, 512>>>(Tg, out);
}

// round 6
// speedup vs baseline: 1.0623x; 1.0623x over previous
#include <cuda_runtime.h>
#include <cuda_bf16.h>
#include <cstdint>

#define M    100000
#define NQ   256
#define D    128
#define KNN  100
#define BB   4
#define TT   64
#define CH   8
#define CHSZ (M / CH)     // 12500
#define CAND 2048
#define TSTR 136          // smem tile stride in bf16 elems (272B, conflict-free)

// ---------------- device scratch ----------------
static __device__ float        g_qn[NQ];
static __device__ float        g_tn[M];
static __device__ __nv_bfloat16 g_qbf[NQ * D];
static __device__ __nv_bfloat16 g_tbf[(size_t)M * D];
static __device__ unsigned int g_key[(size_t)NQ * M];   // approx sortable keys
static __device__ unsigned long long g_part[NQ * CH * KNN];
static __device__ int          g_idx[NQ * KNN];
static __device__ float        g_emit[NQ * KNN];
static __device__ float        g_states[(size_t)NQ * KNN * D];
static __device__ float        g_trans[(size_t)BB * (TT - 1) * KNN * KNN];

__device__ __forceinline__ unsigned int f2key(float f) {
    unsigned int u = __float_as_uint(f);
    return (u & 0x80000000u) ? ~u : (u | 0x80000000u);
}
__device__ __forceinline__ float key2f(unsigned int k) {
    unsigned int u = (k & 0x80000000u) ? (k & 0x7fffffffu) : ~k;
    return __uint_as_float(u);
}

__device__ __forceinline__ void mma_bf16(float* d, const unsigned* a, const unsigned* b) {
    asm volatile(
        "mma.sync.aligned.m16n8k16.row.col.f32.bf16.bf16.f32 "
        "{%0,%1,%2,%3}, {%4,%5,%6,%7}, {%8,%9}, {%0,%1,%2,%3};"
        : "+f"(d[0]), "+f"(d[1]), "+f"(d[2]), "+f"(d[3])
        : "r"(a[0]), "r"(a[1]), "r"(a[2]), "r"(a[3]), "r"(b[0]), "r"(b[1]));
}

// ---------------- norms + bf16 convert (one pass over each input) ----------------
__global__ void norms_kernel(const float* __restrict__ Q, const float* __restrict__ Tg) {
    int i = blockIdx.x * blockDim.x + threadIdx.x;
    if (i < M) {
        const float4* p = (const float4*)(Tg + (size_t)i * D);
        unsigned int* ob = (unsigned int*)(g_tbf + (size_t)i * D);
        float acc = 0.f;
#pragma unroll
        for (int k = 0; k < D / 4; k++) {
            float4 v = p[k];
            acc += v.x * v.x + v.y * v.y + v.z * v.z + v.w * v.w;
            __nv_bfloat162 p0 = __floats2bfloat162_rn(v.x, v.y);
            __nv_bfloat162 p1 = __floats2bfloat162_rn(v.z, v.w);
            ob[k * 2 + 0] = *(unsigned int*)&p0;
            ob[k * 2 + 1] = *(unsigned int*)&p1;
        }
        g_tn[i] = acc;
    } else if (i < M + NQ) {
        int q = i - M;
        const float4* p = (const float4*)(Q + (size_t)q * D);
        unsigned int* ob = (unsigned int*)(g_qbf + (size_t)q * D);
        float acc = 0.f;
#pragma unroll
        for (int k = 0; k < D / 4; k++) {
            float4 v = p[k];
            acc += v.x * v.x + v.y * v.y + v.z * v.z + v.w * v.w;
            __nv_bfloat162 p0 = __floats2bfloat162_rn(v.x, v.y);
            __nv_bfloat162 p1 = __floats2bfloat162_rn(v.z, v.w);
            ob[k * 2 + 0] = *(unsigned int*)&p0;
            ob[k * 2 + 1] = *(unsigned int*)&p1;
        }
        g_qn[q] = acc;
    }
}

// ---------------- approx distance GEMM: bf16 mma.sync m16n8k16 ----------------
// 128(q) x 128(t) tile, K=128 staged once, 8 warps, warp tile 32x64.
__global__ __launch_bounds__(256)
void dist_bf16_kernel() {
    extern __shared__ __align__(16) char dyn[];
    __nv_bfloat16* Qs = (__nv_bfloat16*)dyn;               // [128][TSTR]
    __nv_bfloat16* Ts = Qs + 128 * TSTR;                   // [128][TSTR]
    __shared__ float s_qn[128], s_tn[128];
    int tid = threadIdx.x;
    int q0 = blockIdx.y * 128, t0 = blockIdx.x * 128;

    // stage bf16 tiles (uint4 = 8 bf16 per ld/st)
    for (int i = tid; i < 2048; i += 256) {
        int half = i >> 10;             // 0=Q, 1=T
        int r = (i & 1023) >> 3;        // row 0..127
        int c8 = (i & 7) << 4;          // col 0,16,...,112
        uint4 w = make_uint4(0u, 0u, 0u, 0u);
        uint4 w2 = w;
        if (!half) {
            const uint4* src = (const uint4*)(g_qbf + (size_t)(q0 + r) * D + c8);
            w = src[0]; w2 = src[1];
            uint4* dst = (uint4*)&Qs[r * TSTR + c8];
            dst[0] = w; dst[1] = w2;
        } else {
            if (t0 + r < M) {
                const uint4* src = (const uint4*)(g_tbf + (size_t)(t0 + r) * D + c8);
                w = src[0]; w2 = src[1];
            }
            uint4* dst = (uint4*)&Ts[r * TSTR + c8];
            dst[0] = w; dst[1] = w2;
        }
    }
    if (tid < 128) {
        s_qn[tid] = g_qn[q0 + tid];
        s_tn[tid] = (t0 + tid < M) ? g_tn[t0 + tid] : 0.f;
    }
    __syncthreads();

    int wid = tid >> 5, lane = tid & 31;
    int g = lane >> 2, t = lane & 3;
    int m0 = (wid >> 1) * 32, n0 = (wid & 1) * 64;

    float acc[2][8][4];
#pragma unroll
    for (int mi = 0; mi < 2; mi++)
#pragma unroll
        for (int ni = 0; ni < 8; ni++)
#pragma unroll
            for (int r = 0; r < 4; r++) acc[mi][ni][r] = 0.f;

#pragma unroll
    for (int ks = 0; ks < 8; ks++) {
        int k0 = ks * 16;
        unsigned a[2][4], b[8][2];
#pragma unroll
        for (int mi = 0; mi < 2; mi++) {
            const __nv_bfloat16* base = &Qs[(m0 + mi * 16 + g) * TSTR + k0 + 2 * t];
            a[mi][0] = *(const unsigned*)(base);
            a[mi][1] = *(const unsigned*)(base + 8 * TSTR);
            a[mi][2] = *(const unsigned*)(base + 8);
            a[mi][3] = *(const unsigned*)(base + 8 * TSTR + 8);
        }
#pragma unroll
        for (int ni = 0; ni < 8; ni++) {
            const __nv_bfloat16* base = &Ts[(n0 + ni * 8 + g) * TSTR + k0 + 2 * t];
            b[ni][0] = *(const unsigned*)(base);
            b[ni][1] = *(const unsigned*)(base + 8);
        }
#pragma unroll
        for (int mi = 0; mi < 2; mi++)
#pragma unroll
            for (int ni = 0; ni < 8; ni++)
                mma_bf16(acc[mi][ni], a[mi], b[ni]);
    }

    // epilogue: d = qn + tn - 2*dot -> sortable key, uint2 stores (proven in R4)
#pragma unroll
    for (int mi = 0; mi < 2; mi++)
#pragma unroll
        for (int half = 0; half < 2; half++) {
            int qr = m0 + mi * 16 + g + half * 8;
            float qn = s_qn[qr];
            unsigned int* dst = g_key + (size_t)(q0 + qr) * M;
#pragma unroll
            for (int ni = 0; ni < 8; ni++) {
                int tc = n0 + ni * 8 + 2 * t;
                int gtc = t0 + tc;
                if (gtc + 1 < M) {
                    float d0 = qn + s_tn[tc]     - 2.f * acc[mi][ni][half * 2 + 0];
                    float d1 = qn + s_tn[tc + 1] - 2.f * acc[mi][ni][half * 2 + 1];
                    *(uint2*)&dst[gtc] = make_uint2(f2key(d0), f2key(d1));
                } else if (gtc < M) {
                    float d0 = qn + s_tn[tc] - 2.f * acc[mi][ni][half * 2 + 0];
                    dst[gtc] = f2key(d0);
                }
            }
        }
}

// ---------------- per-chunk: approx radix-select -> candidates -> exact refine ----------------
__global__ void select_part_kernel(const float* __restrict__ Q, const float* __restrict__ Tg) {
    extern __shared__ __align__(16) unsigned int sp[];
    unsigned int* skey = sp;                                    // CHSZ approx keys
    unsigned int* hist = sp + CHSZ;                             // 2048
    unsigned int* cand = hist + 2048;                           // CAND
    unsigned long long* buf = (unsigned long long*)(cand + CAND);
    float* qrow_s = (float*)(buf + CAND);                       // 128
    __shared__ unsigned int scanbuf[256];
    __shared__ unsigned int s_prefix, s_cnt;
    __shared__ int s_kneed;

    int q = blockIdx.y;
    int c0 = blockIdx.x * CHSZ;
    int tid = threadIdx.x;
    const unsigned int* krow = g_key + (size_t)q * M + c0;

    for (int j = tid; j < CHSZ / 4; j += 256)
        *(uint4*)&skey[j * 4] = *(const uint4*)&krow[j * 4];
    if (tid < 32)
        *(float4*)&qrow_s[tid * 4] = *(const float4*)&Q[(size_t)q * D + tid * 4];
    if (tid == 0) { s_prefix = 0u; s_kneed = KNN; }
    __syncthreads();

    const int shifts[3]  = {21, 10, 0};
    const int bitsArr[3] = {11, 11, 10};
    for (int p = 0; p < 3; p++) {
        int shift = shifts[p];
        int nb = 1 << bitsArr[p];
        for (int i = tid; i < nb; i += 256) hist[i] = 0u;
        __syncthreads();
        unsigned int prefix = s_prefix;
        int top = shift + bitsArr[p];
        for (int j = tid; j < CHSZ; j += 256) {
            unsigned int key = skey[j];
            bool ok = (top >= 32) || ((key >> top) == (prefix >> top));
            if (ok) {
                unsigned int bin = (key >> shift) & (unsigned int)(nb - 1);
                unsigned int mm = __match_any_sync(__activemask(), bin);
                if ((int)(tid & 31) == __ffs(mm) - 1) atomicAdd(&hist[bin], (unsigned)__popc(mm));
            }
        }
        __syncthreads();
        int chunk = nb / 256;
        unsigned int ssum = 0u;
        for (int i = 0; i < chunk; i++) ssum += hist[tid * chunk + i];
        scanbuf[tid] = ssum;
        __syncthreads();
        for (int off = 1; off < 256; off <<= 1) {
            unsigned int a = scanbuf[tid];
            unsigned int b = (tid >= off) ? scanbuf[tid - off] : 0u;
            __syncthreads();
            scanbuf[tid] = a + b;
            __syncthreads();
        }
        int kneed = s_kneed;
        unsigned int excl = (tid == 0) ? 0u : scanbuf[tid - 1];
        unsigned int incl = scanbuf[tid];
        __syncthreads();
        if ((int)excl < kneed && kneed <= (int)incl) {
            unsigned int c = excl;
            for (int i = 0; i < chunk; i++) {
                unsigned int h = hist[tid * chunk + i];
                c += h;
                if (kneed <= (int)c) {
                    s_prefix = prefix | ((unsigned int)(tid * chunk + i) << shift);
                    s_kneed = kneed - (int)(c - h);
                    break;
                }
            }
        }
        __syncthreads();
    }

    float dkth = key2f(s_prefix);

    int n = 0;
    for (int att = 0; att < 2; att++) {
        if (tid == 0) s_cnt = 0u;
        __syncthreads();
        unsigned int thresh = f2key(dkth + ((att == 0) ? 4.0f : 0.5f));
        for (int j = tid; j < CHSZ; j += 256) {
            if (skey[j] <= thresh) {
                unsigned int pos = atomicAdd(&s_cnt, 1u);
                if (pos < CAND) cand[pos] = (unsigned int)j;
            }
        }
        __syncthreads();
        n = (int)s_cnt;
        if (n <= CAND) break;
        __syncthreads();
    }
    if (n > CAND) n = CAND;

    // exact fp32 recompute for candidates
    float qn = g_qn[q];
    for (int c = tid; c < n; c += 256) {
        int j = (int)cand[c];
        const float* trow = Tg + (size_t)(c0 + j) * D;
        float a0 = 0.f, a1 = 0.f, a2 = 0.f, a3 = 0.f;
#pragma unroll
        for (int k4 = 0; k4 < 32; k4++) {
            float4 tv = *(const float4*)&trow[k4 * 4];
            float4 qv = *(const float4*)&qrow_s[k4 * 4];
            a0 = fmaf(qv.x, tv.x, a0);
            a1 = fmaf(qv.y, tv.y, a1);
            a2 = fmaf(qv.z, tv.z, a2);
            a3 = fmaf(qv.w, tv.w, a3);
        }
        float d = qn + g_tn[c0 + j] - 2.f * ((a0 + a1) + (a2 + a3));
        buf[c] = ((unsigned long long)f2key(d) << 32) | (unsigned int)(c0 + j);
    }
    __syncthreads();

    int size = 128;
    while (size < n) size <<= 1;
    for (int i = tid; i < size; i += 256)
        if (i >= n) buf[i] = 0xFFFFFFFFFFFFFFFFull;
    __syncthreads();

    for (int k2 = 2; k2 <= size; k2 <<= 1) {
        for (int j2 = k2 >> 1; j2 > 0; j2 >>= 1) {
            for (int i = tid; i < size; i += 256) {
                int l = i ^ j2;
                if (l > i) {
                    unsigned long long a = buf[i], b = buf[l];
                    bool up = ((i & k2) == 0);
                    if ((a > b) == up) { buf[i] = b; buf[l] = a; }
                }
            }
            __syncthreads();
        }
    }

    unsigned long long* dst = g_part + (q * CH + blockIdx.x) * KNN;
    if (tid < KNN) dst[tid] = buf[tid];
}

// ---------------- merge 8x100 chunk winners -> global top-100 ----------------
__global__ void select_merge_kernel() {
    __shared__ unsigned long long buf[1024];
    __shared__ float sred[256];
    __shared__ float s_dmin;
    int q = blockIdx.x;
    int tid = threadIdx.x;
    const unsigned long long* src = g_part + q * CH * KNN;
    for (int i = tid; i < 1024; i += 256)
        buf[i] = (i < CH * KNN) ? src[i] : 0xFFFFFFFFFFFFFFFFull;
    __syncthreads();
    for (int k2 = 2; k2 <= 1024; k2 <<= 1) {
        for (int j2 = k2 >> 1; j2 > 0; j2 >>= 1) {
            for (int i = tid; i < 1024; i += 256) {
                int l = i ^ j2;
                if (l > i) {
                    unsigned long long a = buf[i], b = buf[l];
                    bool up = ((i & k2) == 0);
                    if ((a > b) == up) { buf[i] = b; buf[l] = a; }
                }
            }
            __syncthreads();
        }
    }
    if (tid == 0) s_dmin = key2f((unsigned int)(buf[0] >> 32));
    __syncthreads();
    float dmin = s_dmin;
    float myex = 0.f; int myidx = 0;
    if (tid < KNN) {
        unsigned long long e = buf[tid];
        myidx = (int)(unsigned int)(e & 0xffffffffull);
        float d = key2f((unsigned int)(e >> 32));
        myex = expf(dmin - d);
    }
    sred[tid] = (tid < KNN) ? myex : 0.f;
    __syncthreads();
    for (int off = 128; off > 0; off >>= 1) {
        if (tid < off) sred[tid] += sred[tid + off];
        __syncthreads();
    }
    float ssum = sred[0];
    if (tid < KNN) {
        g_emit[q * KNN + tid] = myex / ssum;
        g_idx[q * KNN + tid] = myidx;
    }
}

// ---------------- states gather ----------------
__global__ void gather_states_kernel(const float* __restrict__ Tg) {
    int n = blockIdx.x * blockDim.x + threadIdx.x;
    if (n >= NQ * KNN * (D / 4)) return;
    int row = n / (D / 4);
    int c = n % (D / 4);
    int tgt = g_idx[row];
    float4 v = *(const float4*)&Tg[(size_t)tgt * D + c * 4];
    *(float4*)&g_states[(size_t)row * D + c * 4] = v;
}

// ---------------- transitions ----------------
__global__ void trans_kernel() {
    extern __shared__ __align__(16) float s[];
    float* sA = s;
    float* sB = s + D * KNN;
    float* an = s + 2 * D * KNN;
    float* bn = an + KNN;
    int bt = blockIdx.x;
    int b = bt / (TT - 1), tl = bt % (TT - 1);
    int qA = b * TT + tl, qB = qA + 1;
    for (int n = threadIdx.x; n < KNN * D; n += blockDim.x) {
        int i = n / D, k = n % D;
        sA[k * KNN + i] = g_states[(size_t)qA * KNN * D + n];
        sB[k * KNN + i] = g_states[(size_t)qB * KNN * D + n];
    }
    __syncthreads();
    for (int i = threadIdx.x; i < 2 * KNN; i += blockDim.x) {
        int ii = (i < KNN) ? i : (i - KNN);
        const float* sp = (i < KNN) ? sA : sB;
        float acc = 0.f;
        for (int k = 0; k < D; k++) { float x = sp[k * KNN + ii]; acc += x * x; }
        if (i < KNN) an[ii] = acc; else bn[ii] = acc;
    }
    __syncthreads();
    float* trow = g_trans + (size_t)bt * KNN * KNN;
    for (int t4 = threadIdx.x; t4 < 625; t4 += blockDim.x) {
        int i0 = (t4 / 25) * 4, j0 = (t4 % 25) * 4;
        float acc[4][4] = {};
        for (int k = 0; k < D; k++) {
            float4 a  = *(const float4*)&sA[k * KNN + i0];
            float4 b4 = *(const float4*)&sB[k * KNN + j0];
            acc[0][0] += a.x * b4.x; acc[0][1] += a.x * b4.y; acc[0][2] += a.x * b4.z; acc[0][3] += a.x * b4.w;
            acc[1][0] += a.y * b4.x; acc[1][1] += a.y * b4.y; acc[1][2] += a.y * b4.z; acc[1][3] += a.y * b4.w;
            acc[2][0] += a.z * b4.x; acc[2][1] += a.z * b4.y; acc[2][2] += a.z * b4.z; acc[2][3] += a.z * b4.w;
            acc[3][0] += a.w * b4.x; acc[3][1] += a.w * b4.y; acc[3][2] += a.w * b4.z; acc[3][3] += a.w * b4.w;
        }
#pragma unroll
        for (int ii = 0; ii < 4; ii++)
#pragma unroll
            for (int jj = 0; jj < 4; jj++) {
                int i = i0 + ii, j = j0 + jj;
                float dd = an[i] + bn[j] - 2.f * acc[ii][jj];
                trow[i * KNN + j] = expf(-dd);
            }
    }
}

// ---------------- viterbi ----------------
__global__ void viterbi_kernel(const float* __restrict__ Tg, float* __restrict__ out) {
    int b = blockIdx.x;
    int tid = threadIdx.x;
    int j = tid & 127, s = tid >> 7;
    __shared__ float v[128];
    __shared__ float part[4][128];
    __shared__ unsigned char parti[4][128];
    __shared__ float red[128];
    __shared__ unsigned char bp[TT - 1][KNN];
    __shared__ int path[TT];
    if (s == 0) v[j] = (j < KNN) ? g_emit[(b * TT) * KNN + j] : 0.f;
    __syncthreads();
    for (int t = 1; t < TT; t++) {
        const float* tr = g_trans + (size_t)(b * (TT - 1) + t - 1) * KNN * KNN;
        float best = -1.f; int back = 0;
        if (j < KNN) {
            int i0 = s * 25;
#pragma unroll
            for (int ii = 0; ii < 25; ii++) {
                int i = i0 + ii;
                float sc = v[i] * tr[i * KNN + j];
                if (sc > best) { best = sc; back = i; }
            }
        }
        part[s][j] = best; parti[s][j] = (unsigned char)back;
        __syncthreads();
        if (s == 0) {
            float em = (j < KNN) ? g_emit[(b * TT + t) * KNN + j] : 0.f;
            float bb = part[0][j]; int bk = parti[0][j];
#pragma unroll
            for (int ss = 1; ss < 4; ss++)
                if (part[ss][j] > bb) { bb = part[ss][j]; bk = parti[ss][j]; }
            if (j < KNN) bp[t - 1][j] = (unsigned char)bk;
            float vn = (j < KNN) ? bb * em : 0.f;
            red[j] = vn;
            part[0][j] = vn;
        }
        __syncthreads();
        for (int off = 64; off > 0; off >>= 1) {
            if (tid < off) red[tid] = fmaxf(red[tid], red[tid + off]);
            __syncthreads();
        }
        float m = fmaxf(red[0], 1e-30f);
        __syncthreads();
        if (s == 0) v[j] = part[0][j] / m;
        __syncthreads();
    }
    if (tid == 0) {
        float bv = v[0]; int last = 0;
        for (int jj = 1; jj < KNN; jj++) if (v[jj] > bv) { bv = v[jj]; last = jj; }
        path[TT - 1] = last;
        int idx = last;
        for (int t = TT - 2; t >= 0; t--) { idx = bp[t][idx]; path[t] = idx; }
    }
    __syncthreads();
    for (int n = tid; n < TT * D; n += 512) {
        int t = n / D, d2 = n % D;
        int row = g_idx[(b * TT + t) * KNN + path[t]];
        out[(size_t)(b * TT + t) * D + d2] = Tg[(size_t)row * D + d2];
    }
}

// ---------------- launch ----------------
extern "C" void kernel_launch(void* const* d_in, const int* in_sizes, int n_in,
                              void* d_out, int out_size) {
    (void)in_sizes; (void)n_in; (void)out_size;
    const float* Q  = (const float*)d_in[0];
    const float* Tg = (const float*)d_in[1];
    float* out = (float*)d_out;

    const int trans_smem = (2 * D * KNN + 2 * KNN) * (int)sizeof(float);      // 103200 B
    const int dist_smem  = 2 * 128 * TSTR * 2;                                // 69632 B
    const int part_smem  = (CHSZ + 2048 + CAND) * 4 + CAND * 8 + 128 * 4;     // 83280 B
    cudaFuncSetAttribute(trans_kernel, cudaFuncAttributeMaxDynamicSharedMemorySize, trans_smem);
    cudaFuncSetAttribute(dist_bf16_kernel, cudaFuncAttributeMaxDynamicSharedMemorySize, dist_smem);
    cudaFuncSetAttribute(select_part_kernel, cudaFuncAttributeMaxDynamicSharedMemorySize, part_smem);

    norms_kernel<<<(M + NQ + 255) / 256, 256>>>(Q, Tg);
    dist_bf16_kernel<<<dim3((M + 127) / 128, NQ / 128), 256, dist_smem>>>();
    select_part_kernel<<<dim3(CH, NQ), 256, part_smem>>>(Q, Tg);
    select_merge_kernel<<<NQ, 256>>>();
    gather_states_kernel<<<(NQ * KNN * (D / 4) + 255) / 256, 256>>>(Tg);
    trans_kernel<<<BB * (TT - 1), 256, trans_smem>>>();
    viterbi_kernel<<<BB, 512>>>(Tg, out);
}